// round 1
// baseline (speedup 1.0000x reference)
#include <cuda_runtime.h>
#include <cuda_bf16.h>
#include <math.h>

// ElasticTransformLayer: 2048x4096x3 fp32 image, 2x3x3 control displacement.
// out[h,w,c] = sum_{a,b in 4x4} wy[a]*wx[b]*img[clamp(iy0+a-1), clamp(ix0+b-1), c]
// with (yy,xx) = (h,w) + 5 * bicubic-spline-upsampled displacement.

#define IMG_H 2048
#define IMG_W 4096
#define IMG_C 3

__device__ __forceinline__ float cubic_w(float t) {
    // Keys cubic, a = -0.5, matching reference branch structure (|t|<=1 inner).
    float at  = fabsf(t);
    float at2 = at * at;
    float at3 = at2 * at;
    const float a = -0.5f;
    float w_inner = (a + 2.0f) * at3 - (a + 3.0f) * at2 + 1.0f;
    float w_outer = a * at3 - 5.0f * a * at2 + 8.0f * a * at - 4.0f * a;
    return (at <= 1.0f) ? w_inner : ((at < 2.0f) ? w_outer : 0.0f);
}

// 3-control-point spline weights for output index i on an axis of length n:
// u = i * 2/(n-1); taps i0-1..i0+2 clamped to [0,2], weights accumulated.
__device__ __forceinline__ void ctrl_weights3(int i, float inv_scale, float w3[3]) {
    w3[0] = 0.0f; w3[1] = 0.0f; w3[2] = 0.0f;
    float u  = (float)i * inv_scale;        // in [0, 2]
    int   i0 = (int)floorf(u);
    #pragma unroll
    for (int a = -1; a < 3; a++) {
        int   tap = i0 + a;
        float wv  = cubic_w(u - (float)tap);
        int   tc  = min(max(tap, 0), 2);
        w3[tc] += wv;
    }
}

__global__ __launch_bounds__(256)
void elastic_warp_kernel(const float* __restrict__ img,
                         const float* __restrict__ dispc,  // (2,3,3) = 18 floats
                         float* __restrict__ out) {
    int w = blockIdx.x * blockDim.x + threadIdx.x;
    int h = blockIdx.y * blockDim.y + threadIdx.y;
    if (w >= IMG_W || h >= IMG_H) return;

    // --- spline control weights along each axis (registers, ~free) ---
    float wy3[3], wx3[3];
    ctrl_weights3(h, 2.0f / (float)(IMG_H - 1), wy3);
    ctrl_weights3(w, 2.0f / (float)(IMG_W - 1), wx3);

    // --- displacement einsum: disp_d = By . (D_d) . Bx, then *5 ---
    float dy = 0.0f, dx = 0.0f;
    #pragma unroll
    for (int y = 0; y < 3; y++) {
        #pragma unroll
        for (int x = 0; x < 3; x++) {
            float bw = wy3[y] * wx3[x];
            dy += bw * __ldg(&dispc[y * 3 + x]);
            dx += bw * __ldg(&dispc[9 + y * 3 + x]);
        }
    }
    dy *= 5.0f;
    dx *= 5.0f;

    // --- sample coordinates and Keys tap weights ---
    float yy = (float)h + dy;
    float xx = (float)w + dx;
    float iy0f = floorf(yy), ix0f = floorf(xx);
    int   iy0 = (int)iy0f,   ix0 = (int)ix0f;
    float fy = yy - iy0f,    fx = xx - ix0f;   // in [0,1)

    float wy[4], wx[4];
    #pragma unroll
    for (int a = 0; a < 4; a++) {
        wy[a] = cubic_w(fy - (float)(a - 1));
        wx[a] = cubic_w(fx - (float)(a - 1));
    }

    // --- 4x4 gather, 3 channels ---
    float acc0 = 0.0f, acc1 = 0.0f, acc2 = 0.0f;
    #pragma unroll
    for (int a = 0; a < 4; a++) {
        int ty = min(max(iy0 + a - 1, 0), IMG_H - 1);
        const float* rowp = img + (size_t)ty * (IMG_W * IMG_C);
        float r0 = 0.0f, r1 = 0.0f, r2 = 0.0f;
        #pragma unroll
        for (int b = 0; b < 4; b++) {
            int tx = min(max(ix0 + b - 1, 0), IMG_W - 1);
            const float* p = rowp + tx * IMG_C;
            float wv = wx[b];
            r0 += wv * __ldg(p + 0);
            r1 += wv * __ldg(p + 1);
            r2 += wv * __ldg(p + 2);
        }
        acc0 += wy[a] * r0;
        acc1 += wy[a] * r1;
        acc2 += wy[a] * r2;
    }

    size_t o = ((size_t)h * IMG_W + (size_t)w) * IMG_C;
    out[o + 0] = acc0;
    out[o + 1] = acc1;
    out[o + 2] = acc2;
}

extern "C" void kernel_launch(void* const* d_in, const int* in_sizes, int n_in,
                              void* d_out, int out_size) {
    const float* img   = (const float*)d_in[0];   // (2048, 4096, 3) fp32
    const float* dispc = (const float*)d_in[1];   // (2, 3, 3) fp32
    float*       out   = (float*)d_out;

    dim3 block(64, 4, 1);
    dim3 grid(IMG_W / 64, IMG_H / 4, 1);
    elastic_warp_kernel<<<grid, block>>>(img, dispc, out);
}

// round 2
// speedup vs baseline: 1.8081x; 1.8081x over previous
#include <cuda_runtime.h>
#include <cuda_bf16.h>
#include <math.h>

#define IMG_H 2048
#define IMG_W 4096
#define IMG_C 3
#define ROW_BYTES (IMG_W * IMG_C * 4)   // 49152

// Precomputed separable tables.
__device__ float g_bx[IMG_W * 3];    // x-axis control weights
__device__ float g_rdy[IMG_H * 3];   // 5 * sum_y wy3[y]*D[0][y][x], per row
__device__ float g_rdx[IMG_H * 3];   // 5 * sum_y wy3[y]*D[1][y][x], per row

__device__ __forceinline__ float cubic_w(float t) {
    float at  = fabsf(t);
    float at2 = at * at;
    float at3 = at2 * at;
    const float a = -0.5f;
    float w_inner = (a + 2.0f) * at3 - (a + 3.0f) * at2 + 1.0f;
    float w_outer = a * at3 - 5.0f * a * at2 + 8.0f * a * at - 4.0f * a;
    return (at <= 1.0f) ? w_inner : ((at < 2.0f) ? w_outer : 0.0f);
}

__device__ __forceinline__ void ctrl_weights3(int i, float inv_scale, float w3[3]) {
    w3[0] = 0.0f; w3[1] = 0.0f; w3[2] = 0.0f;
    float u  = (float)i * inv_scale;
    int   i0 = (int)floorf(u);
    #pragma unroll
    for (int a = -1; a < 3; a++) {
        int   tap = i0 + a;
        float wv  = cubic_w(u - (float)tap);
        int   tc  = min(max(tap, 0), 2);
        w3[tc] += wv;
    }
}

__global__ void setup_tables(const float* __restrict__ dispc) {
    int i = blockIdx.x * blockDim.x + threadIdx.x;
    if (i < IMG_W) {
        float w3[3];
        ctrl_weights3(i, 2.0f / (float)(IMG_W - 1), w3);
        g_bx[i * 3 + 0] = w3[0];
        g_bx[i * 3 + 1] = w3[1];
        g_bx[i * 3 + 2] = w3[2];
    }
    if (i < IMG_H) {
        float w3[3];
        ctrl_weights3(i, 2.0f / (float)(IMG_H - 1), w3);
        #pragma unroll
        for (int x = 0; x < 3; x++) {
            float ry = w3[0] * dispc[0 * 3 + x] + w3[1] * dispc[3 + x] + w3[2] * dispc[6 + x];
            float rx = w3[0] * dispc[9 + x]     + w3[1] * dispc[12 + x] + w3[2] * dispc[15 + x];
            g_rdy[i * 3 + x] = 5.0f * ry;
            g_rdx[i * 3 + x] = 5.0f * rx;
        }
    }
}

// Closed-form Keys (a=-0.5) tap weights for frac t in [0,1):
//   w[-1] = -0.5*t*(1-t)^2, w[0] = (1.5t-2.5)t^2+1, w[1] = (1.5s-2.5)s^2+1, w[2] = -0.5*t^2*(1-t)
__device__ __forceinline__ void keys_weights(float t, float w[4]) {
    float s  = 1.0f - t;
    float tt = t * t;
    float ss = s * s;
    w[0] = -0.5f * t * ss;
    w[1] = fmaf(fmaf(1.5f, t, -2.5f), tt, 1.0f);
    w[2] = fmaf(fmaf(1.5f, s, -2.5f), ss, 1.0f);
    w[3] = -0.5f * tt * s;
}

__global__ __launch_bounds__(256)
void elastic_warp_kernel(const float* __restrict__ img,
                         float* __restrict__ out) {
    int w = blockIdx.x * blockDim.x + threadIdx.x;
    int h = blockIdx.y * blockDim.y + threadIdx.y;

    // Displacement from separable tables: 6 FMAs.
    float bx0 = g_bx[w * 3 + 0], bx1 = g_bx[w * 3 + 1], bx2 = g_bx[w * 3 + 2];
    float dy = g_rdy[h * 3 + 0] * bx0 + g_rdy[h * 3 + 1] * bx1 + g_rdy[h * 3 + 2] * bx2;
    float dx = g_rdx[h * 3 + 0] * bx0 + g_rdx[h * 3 + 1] * bx1 + g_rdx[h * 3 + 2] * bx2;

    float yy = (float)h + dy;
    float xx = (float)w + dx;
    float iy0f = floorf(yy), ix0f = floorf(xx);
    int   iy0 = (int)iy0f,   ix0 = (int)ix0f;
    float fy = yy - iy0f,    fx = xx - ix0f;

    float wy[4], wx[4];
    keys_weights(fy, wy);
    keys_weights(fx, wx);

    // Clamped byte offsets, computed once.
    int coff[4];
    #pragma unroll
    for (int b = 0; b < 4; b++) {
        int tx = min(max(ix0 + b - 1, 0), IMG_W - 1);
        coff[b] = tx * (IMG_C * 4);
    }
    const char* ibase = (const char*)img;
    const char* rowp[4];
    #pragma unroll
    for (int a = 0; a < 4; a++) {
        int ty = min(max(iy0 + a - 1, 0), IMG_H - 1);
        rowp[a] = ibase + (unsigned)ty * ROW_BYTES;
    }

    float acc0 = 0.0f, acc1 = 0.0f, acc2 = 0.0f;
    #pragma unroll
    for (int a = 0; a < 4; a++) {
        float r0 = 0.0f, r1 = 0.0f, r2 = 0.0f;
        #pragma unroll
        for (int b = 0; b < 4; b++) {
            const float* p = (const float*)(rowp[a] + coff[b]);
            float wv = wx[b];
            r0 = fmaf(wv, __ldg(p + 0), r0);
            r1 = fmaf(wv, __ldg(p + 1), r1);
            r2 = fmaf(wv, __ldg(p + 2), r2);
        }
        acc0 = fmaf(wy[a], r0, acc0);
        acc1 = fmaf(wy[a], r1, acc1);
        acc2 = fmaf(wy[a], r2, acc2);
    }

    size_t o = ((size_t)h * IMG_W + (size_t)w) * IMG_C;
    out[o + 0] = acc0;
    out[o + 1] = acc1;
    out[o + 2] = acc2;
}

extern "C" void kernel_launch(void* const* d_in, const int* in_sizes, int n_in,
                              void* d_out, int out_size) {
    const float* img   = (const float*)d_in[0];   // (2048, 4096, 3) fp32
    const float* dispc = (const float*)d_in[1];   // (2, 3, 3) fp32
    float*       out   = (float*)d_out;

    setup_tables<<<(IMG_W + 255) / 256, 256>>>(dispc);

    dim3 block(64, 4, 1);
    dim3 grid(IMG_W / 64, IMG_H / 4, 1);
    elastic_warp_kernel<<<grid, block>>>(img, out);
}